// round 14
// baseline (speedup 1.0000x reference)
#include <cuda_runtime.h>
#include <cstdint>

#define S_      7
#define SS_     49
#define BATCH_  16384
#define D_      30
#define NCELL_  (BATCH_ * SS_)         /* 802816 */
#define CPB_    128                    /* cells per tile */
#define BLK_    192                    /* threads per block */
#define NBLK_   296                    /* persistent blocks = 2 x 148 SMs */
#define NT_     (NCELL_ / CPB_)        /* 6272 tiles */
#define TILE_W  (CPB_ * D_)            /* 3840 floats */
#define TILE_B  (TILE_W * 4)           /* 15360 bytes per tensor tile */
#define STAGE_W (TILE_W * 2)
#define STAGE_B (TILE_B * 2)           /* 30720 bytes */
#define NSTG_   3
#define SMEM_BYTES (NSTG_ * STAGE_B)   /* 92160 */
#define RCSTEP_ 11                     /* (NBLK_*CPB_) % 49 */
#define OUT_BLKS_ 256
#define BPO_    64                     /* 256*64 = 16384; 64*49*4B 16B-aligned */
#define OUT_V   (BPO_ * SS_ / 4)       /* 784 float4 */

__device__ float g_A[SS_];
__device__ float g_C;
__device__ float g_has[NCELL_];
__device__ int   g_barrier;            /* static 0; self-resets */
__device__ int   g_done;               /* static 0; self-resets */

__device__ __forceinline__ float scalar_to_float(const void* p) {
    int v = *(const int*)p;
    if (v > 0 && v < 1000000) return (float)v;
    return __int_as_float(v);
}

__device__ __forceinline__ float iou_fn(float cx, float cy, float w, float h,
                                        float tx0, float ty0, float tx1, float ty1,
                                        float areaT) {
    float hw = w * 0.5f, hh = h * 0.5f;
    float x0 = cx - hw, x1 = cx + hw;
    float y0 = cy - hh, y1 = cy + hh;
    float iw = fmaxf(fminf(x1, tx1) - fmaxf(x0, tx0), 0.0f);
    float ih = fmaxf(fminf(y1, ty1) - fmaxf(y0, ty0), 0.0f);
    float inter = iw * ih;
    float area_a = (x1 - x0) * (y1 - y0);
    return inter / (area_a + areaT - inter + 1e-9f);
}

__device__ __forceinline__ void mbar_init(uint32_t mbar, uint32_t cnt) {
    asm volatile("mbarrier.init.shared.b64 [%0], %1;" :: "r"(mbar), "r"(cnt) : "memory");
}
__device__ __forceinline__ void mbar_expect_tx(uint32_t mbar, uint32_t bytes) {
    asm volatile("mbarrier.arrive.expect_tx.shared.b64 _, [%0], %1;"
                 :: "r"(mbar), "r"(bytes) : "memory");
}
__device__ __forceinline__ void bulk_g2s(uint32_t dst, const void* src,
                                         uint32_t bytes, uint32_t mbar) {
    asm volatile("cp.async.bulk.shared::cluster.global.mbarrier::complete_tx::bytes "
                 "[%0], [%1], %2, [%3];"
                 :: "r"(dst), "l"(src), "r"(bytes), "r"(mbar) : "memory");
}
__device__ __forceinline__ void mbar_wait(uint32_t mbar, uint32_t parity) {
    uint32_t done;
    asm volatile("{\n\t.reg .pred p;\n\t"
                 "mbarrier.try_wait.parity.acquire.cta.shared::cta.b64 p, [%1], %2;\n\t"
                 "selp.b32 %0, 1, 0, p;\n\t}"
                 : "=r"(done) : "r"(mbar), "r"(parity) : "memory");
    if (!done) {
        asm volatile("{\n\t.reg .pred P1;\n\t"
                     "WL_%=:\n\t"
                     "mbarrier.try_wait.parity.acquire.cta.shared::cta.b64 P1, [%0], %1, 0x989680;\n\t"
                     "@P1 bra.uni WD_%=;\n\t"
                     "bra.uni WL_%=;\n\t"
                     "WD_%=:\n\t}"
                     :: "r"(mbar), "r"(parity) : "memory");
    }
}

extern __shared__ float dynsmem[];

__global__ __launch_bounds__(BLK_) void yolo_kernel(
    const float* __restrict__ outp, const float* __restrict__ tgt,
    const void* __restrict__ iwp, const void* __restrict__ ihp,
    float* __restrict__ lossOut)
{
    __shared__ __align__(8) unsigned long long mbar_store[NSTG_];
    __shared__ float sA_blk[SS_];
    __shared__ float sC_blk;
    __shared__ float sAfin[SS_ + 1];

    const float W = scalar_to_float(iwp);
    const float H = scalar_to_float(ihp);
    const float csx = W / 7.0f, csy = H / 7.0f;

    const int tid = threadIdx.x;
    const int bid = blockIdx.x;
    const uint32_t sbase = (uint32_t)__cvta_generic_to_shared(dynsmem);
    const uint32_t mb0   = (uint32_t)__cvta_generic_to_shared(mbar_store);

    if (tid < SS_) sA_blk[tid] = 0.0f;
    if (tid == 64) sC_blk = 0.0f;
    if (tid == 0) {
#pragma unroll
        for (int s = 0; s < NSTG_; s++) mbar_init(mb0 + s * 8, 1);
        asm volatile("fence.proxy.async.shared::cta;" ::: "memory");
    }
    __syncthreads();

    const int nt = (NT_ - bid + NBLK_ - 1) / NBLK_;   /* 21 or 22 tiles */

    const char* gob = (const char*)(outp + (size_t)bid * TILE_W);
    const char* gtb = (const char*)(tgt  + (size_t)bid * TILE_W);

#define ISSUE_TILE(k, s) do {                                                  \
        uint32_t bar = mb0 + (s) * 8;                                          \
        uint32_t dst = sbase + (s) * STAGE_B;                                  \
        mbar_expect_tx(bar, STAGE_B);                                          \
        bulk_g2s(dst,          gob + (size_t)(k) * (NBLK_ * TILE_B), TILE_B, bar); \
        bulk_g2s(dst + TILE_B, gtb + (size_t)(k) * (NBLK_ * TILE_B), TILE_B, bar); \
    } while (0)

    if (tid == 0) {
        ISSUE_TILE(0, 0);
        ISSUE_TILE(1, 1);
    }

    float accC = 0.0f;
    int rc = (bid * CPB_ + tid) % SS_;     /* advances +11 mod 49 per tile */

    for (int k = 0; k < nt; k++) {
        /* refill stage (k+2)%3: safe, tile k-1's readers left it last iter */
        if (tid == 0 && k + 2 < nt) ISSUE_TILE(k + 2, (k + 2) % NSTG_);

        const int stg = k % NSTG_;
        mbar_wait(mb0 + stg * 8, (k / 3) & 1);

        const float* so = dynsmem + stg * STAGE_W;
        const float* st = so + TILE_W;

        if (tid < CPB_) {
            const int cell = (bid + k * NBLK_) * CPB_ + tid;
            const float rr = (float)(rc / S_);
            const float cc = (float)(rc - (rc / S_) * S_);

            const float2* o2 = (const float2*)(so + tid * D_);
            const float2* t2 = (const float2*)(st + tid * D_);

            float2 oa = o2[0], ob = o2[1], oc = o2[2], od = o2[3], oe = o2[4];
            float2 ta = t2[0], tb = t2[1], tc = t2[2];

            float o0 = oa.x, o1 = oa.y, o3 = ob.y, o4 = oc.x;
            float o5 = oc.y, o6 = od.x, o8 = oe.x, o9 = oe.y;

            float tx = ta.x, ty = ta.y;
            float tw = tb.x * W, th = tb.y * H;
            float has = tc.x;

            g_has[cell] = has;

            float cxt = (cc + tx) * csx, cyt = (rr + ty) * csy;
            float htw = tw * 0.5f, hth = th * 0.5f;
            float tx0 = cxt - htw, tx1 = cxt + htw;
            float ty0 = cyt - hth, ty1 = cyt + hth;
            float areaT = (tx1 - tx0) * (ty1 - ty0);

            float iou0 = iou_fn((cc + o0) * csx, (rr + o1) * csy, o3 * W, o4 * H,
                                tx0, ty0, tx1, ty1, areaT);
            float iou1 = iou_fn((cc + o5) * csx, (rr + o6) * csy, o8 * W, o9 * H,
                                tx0, ty0, tx1, ty1, areaT);

            float bc = (iou1 >= iou0) ? o9 : o4;   /* last argmax per reference */

            float cls = 0.0f;
#pragma unroll
            for (int kk = 0; kk < 10; kk++) {
                float2 ock = o2[5 + kk];
                float2 tck = t2[5 + kk];
                float d0 = tck.x - ock.x * bc;
                float d1 = tck.y - ock.y * bc;
                cls += d0 * d0 + d1 * d1;
            }

            float dx  = tx - o5;
            float dy  = ty - o6;
            float swd = sqrtf(tw) - sqrtf(o8 * W);
            float shd = sqrtf(th) - sqrtf(o9 * H);
            float dcf = has - o9;
            float confsq = dcf * dcf;

            float accA = 5.0f * (dx * dx + dy * dy + swd * swd + shd * shd)
                       + 0.5f * confsq;
            accC += 0.5f * confsq + cls;

            atomicAdd(&sA_blk[rc], accA);

            rc += RCSTEP_;
            if (rc >= SS_) rc -= SS_;
        }
        __syncthreads();                   /* stage readers done -> reusable */
    }

    /* block reduction of C */
#pragma unroll
    for (int off = 16; off > 0; off >>= 1)
        accC += __shfl_down_sync(0xFFFFFFFFu, accC, off);
    if ((tid & 31) == 0) atomicAdd(&sC_blk, accC);
    __syncthreads();

    if (tid < SS_) atomicAdd(&g_A[tid], sA_blk[tid]);
    if (tid == 64) atomicAdd(&g_C, sC_blk);

    /* ---------------- grid-wide barrier ---------------- */
    __threadfence();
    __syncthreads();
    if (tid == 0) {
        atomicAdd(&g_barrier, 1);
        while (*(volatile int*)&g_barrier < NBLK_) { __nanosleep(32); }
    }
    __syncthreads();

    /* ---------------- phase 2: 256 blocks x 64 batches ---------------- */
    int arrive_old = 0;
    if (bid < OUT_BLKS_) {
        if (tid < SS_) sAfin[tid] = g_A[tid];
        if (tid == 64) sAfin[SS_] = g_C;

        const float4* gh4 = (const float4*)(g_has + (size_t)bid * BPO_ * SS_);
        float4* sh4 = (float4*)dynsmem;
#pragma unroll
        for (int j = 0; j < 5; j++) {
            int idx = j * BLK_ + tid;
            if (idx < OUT_V) sh4[idx] = gh4[idx];
        }
        __syncthreads();

        if (tid == 0) arrive_old = atomicAdd(&g_done, 1);

        if (tid < BPO_) {
            const float* hb = dynsmem + tid * SS_;   /* stride 49: conflict-free */
            float s = 0.0f;
#pragma unroll
            for (int r = 0; r < SS_; r++)
                s += hb[r] * sAfin[r];
            lossOut[bid * BPO_ + tid] = s + sAfin[SS_];
        }
    } else {
        if (tid == 0) arrive_old = atomicAdd(&g_done, 1);
    }

    if (tid == 0 && arrive_old == NBLK_ - 1) {
#pragma unroll
        for (int i = 0; i < SS_; i++) g_A[i] = 0.0f;
        g_C = 0.0f;
        g_barrier = 0;
        g_done = 0;
    }
}

extern "C" void kernel_launch(void* const* d_in, const int* in_sizes, int n_in,
                              void* d_out, int out_size)
{
    const float* o  = (const float*)d_in[0];
    const float* t  = (const float*)d_in[1];
    const void*  iw = d_in[2];
    const void*  ih = d_in[3];

    cudaFuncSetAttribute(yolo_kernel,
                         cudaFuncAttributeMaxDynamicSharedMemorySize, SMEM_BYTES);
    yolo_kernel<<<NBLK_, BLK_, SMEM_BYTES>>>(o, t, iw, ih, (float*)d_out);
}

// round 15
// speedup vs baseline: 1.0526x; 1.0526x over previous
#include <cuda_runtime.h>
#include <cstdint>

#define S_      7
#define SS_     49
#define BATCH_  16384
#define D_      30
#define NCELL_  (BATCH_ * SS_)         /* 802816 */
#define CPB_    128                    /* cells per tile */
#define BLK_    128                    /* threads per block (all compute) */
#define NBLK_   444                    /* persistent blocks = 3 x 148 SMs */
#define NT_     (NCELL_ / CPB_)        /* 6272 tiles */
#define TILE_W  (CPB_ * D_)            /* 3840 floats */
#define TILE_B  (TILE_W * 4)           /* 15360 bytes per tensor tile */
#define STAGE_W (TILE_W * 2)
#define STAGE_B (TILE_B * 2)           /* 30720 bytes */
#define NSTG_   2
#define SMEM_BYTES (NSTG_ * STAGE_B)   /* 61440 -> 3 blocks/SM */
#define OUT_BLKS_ 256
#define BPO_    64                     /* 256*64 = 16384; 64*49*4B 16B-aligned */
#define OUT_V   (BPO_ * SS_ / 4)       /* 784 float4 */

__device__ float g_A[SS_];
__device__ float g_C;
__device__ float g_has[NCELL_];
__device__ int   g_tile;               /* work-steal counter; self-resets */
__device__ int   g_barrier;            /* static 0; self-resets */
__device__ int   g_done;               /* static 0; self-resets */

__device__ __forceinline__ float scalar_to_float(const void* p) {
    int v = *(const int*)p;
    if (v > 0 && v < 1000000) return (float)v;
    return __int_as_float(v);
}

__device__ __forceinline__ float iou_fn(float cx, float cy, float w, float h,
                                        float tx0, float ty0, float tx1, float ty1,
                                        float areaT) {
    float hw = w * 0.5f, hh = h * 0.5f;
    float x0 = cx - hw, x1 = cx + hw;
    float y0 = cy - hh, y1 = cy + hh;
    float iw = fmaxf(fminf(x1, tx1) - fmaxf(x0, tx0), 0.0f);
    float ih = fmaxf(fminf(y1, ty1) - fmaxf(y0, ty0), 0.0f);
    float inter = iw * ih;
    float area_a = (x1 - x0) * (y1 - y0);
    return inter / (area_a + areaT - inter + 1e-9f);
}

__device__ __forceinline__ void mbar_init(uint32_t mbar, uint32_t cnt) {
    asm volatile("mbarrier.init.shared.b64 [%0], %1;" :: "r"(mbar), "r"(cnt) : "memory");
}
__device__ __forceinline__ void mbar_expect_tx(uint32_t mbar, uint32_t bytes) {
    asm volatile("mbarrier.arrive.expect_tx.shared.b64 _, [%0], %1;"
                 :: "r"(mbar), "r"(bytes) : "memory");
}
__device__ __forceinline__ void bulk_g2s(uint32_t dst, const void* src,
                                         uint32_t bytes, uint32_t mbar) {
    asm volatile("cp.async.bulk.shared::cluster.global.mbarrier::complete_tx::bytes "
                 "[%0], [%1], %2, [%3];"
                 :: "r"(dst), "l"(src), "r"(bytes), "r"(mbar) : "memory");
}
__device__ __forceinline__ void mbar_wait(uint32_t mbar, uint32_t parity) {
    uint32_t done;
    asm volatile("{\n\t.reg .pred p;\n\t"
                 "mbarrier.try_wait.parity.acquire.cta.shared::cta.b64 p, [%1], %2;\n\t"
                 "selp.b32 %0, 1, 0, p;\n\t}"
                 : "=r"(done) : "r"(mbar), "r"(parity) : "memory");
    if (!done) {
        asm volatile("{\n\t.reg .pred P1;\n\t"
                     "WL_%=:\n\t"
                     "mbarrier.try_wait.parity.acquire.cta.shared::cta.b64 P1, [%0], %1, 0x989680;\n\t"
                     "@P1 bra.uni WD_%=;\n\t"
                     "bra.uni WL_%=;\n\t"
                     "WD_%=:\n\t}"
                     :: "r"(mbar), "r"(parity) : "memory");
    }
}

extern __shared__ float dynsmem[];

__global__ __launch_bounds__(BLK_, 3) void yolo_kernel(
    const float* __restrict__ outp, const float* __restrict__ tgt,
    const void* __restrict__ iwp, const void* __restrict__ ihp,
    float* __restrict__ lossOut)
{
    __shared__ __align__(8) unsigned long long mbar_store[NSTG_];
    __shared__ int   sTile[NSTG_];
    __shared__ float sA_blk[SS_];
    __shared__ float sC_blk;
    __shared__ float sAfin[SS_ + 1];

    const float W = scalar_to_float(iwp);
    const float H = scalar_to_float(ihp);
    const float csx = W / 7.0f, csy = H / 7.0f;

    const int tid = threadIdx.x;
    const int bid = blockIdx.x;
    const uint32_t sbase = (uint32_t)__cvta_generic_to_shared(dynsmem);
    const uint32_t mb0   = (uint32_t)__cvta_generic_to_shared(mbar_store);

    if (tid < SS_) sA_blk[tid] = 0.0f;
    if (tid == 64) sC_blk = 0.0f;
    if (tid == 0) {
#pragma unroll
        for (int s = 0; s < NSTG_; s++) mbar_init(mb0 + s * 8, 1);
        asm volatile("fence.proxy.async.shared::cta;" ::: "memory");
    }
    __syncthreads();

#define ISSUE_TILE(t, s) do {                                                  \
        uint32_t bar = mb0 + (s) * 8;                                          \
        uint32_t dst = sbase + (s) * STAGE_B;                                  \
        mbar_expect_tx(bar, STAGE_B);                                          \
        bulk_g2s(dst,          (const char*)outp + (size_t)(t) * TILE_B, TILE_B, bar); \
        bulk_g2s(dst + TILE_B, (const char*)tgt  + (size_t)(t) * TILE_B, TILE_B, bar); \
    } while (0)

    /* prefetch: steal two tiles */
    if (tid == 0) {
        int t0 = atomicAdd(&g_tile, 1);
        sTile[0] = t0;
        if (t0 < NT_) ISSUE_TILE(t0, 0);
        int t1 = atomicAdd(&g_tile, 1);
        sTile[1] = t1;
        if (t1 < NT_) ISSUE_TILE(t1, 1);
    }
    __syncthreads();

    float accC = 0.0f;

    for (int k = 0; ; k++) {
        const int stg = k & 1;
        const int tk = sTile[stg];
        if (tk >= NT_) break;

        mbar_wait(mb0 + stg * 8, (k >> 1) & 1);

        const float* so = dynsmem + stg * STAGE_W;
        const float* st = so + TILE_W;

        {
            const int cell = tk * CPB_ + tid;
            const int rc = cell % SS_;
            const int rci = rc / S_;
            const float rr = (float)rci;
            const float cc = (float)(rc - rci * S_);

            const float2* o2 = (const float2*)(so + tid * D_);
            const float2* t2 = (const float2*)(st + tid * D_);

            float2 oa = o2[0], ob = o2[1], oc = o2[2], od = o2[3], oe = o2[4];
            float2 ta = t2[0], tb = t2[1], tc = t2[2];

            float o0 = oa.x, o1 = oa.y, o3 = ob.y, o4 = oc.x;
            float o5 = oc.y, o6 = od.x, o8 = oe.x, o9 = oe.y;

            float tx = ta.x, ty = ta.y;
            float tw = tb.x * W, th = tb.y * H;
            float has = tc.x;

            g_has[cell] = has;

            float cxt = (cc + tx) * csx, cyt = (rr + ty) * csy;
            float htw = tw * 0.5f, hth = th * 0.5f;
            float tx0 = cxt - htw, tx1 = cxt + htw;
            float ty0 = cyt - hth, ty1 = cyt + hth;
            float areaT = (tx1 - tx0) * (ty1 - ty0);

            float iou0 = iou_fn((cc + o0) * csx, (rr + o1) * csy, o3 * W, o4 * H,
                                tx0, ty0, tx1, ty1, areaT);
            float iou1 = iou_fn((cc + o5) * csx, (rr + o6) * csy, o8 * W, o9 * H,
                                tx0, ty0, tx1, ty1, areaT);

            float bc = (iou1 >= iou0) ? o9 : o4;   /* last argmax per reference */

            float cls = 0.0f;
#pragma unroll
            for (int kk = 0; kk < 10; kk++) {
                float2 ock = o2[5 + kk];
                float2 tck = t2[5 + kk];
                float d0 = tck.x - ock.x * bc;
                float d1 = tck.y - ock.y * bc;
                cls += d0 * d0 + d1 * d1;
            }

            float dx  = tx - o5;
            float dy  = ty - o6;
            float swd = sqrtf(tw) - sqrtf(o8 * W);
            float shd = sqrtf(th) - sqrtf(o9 * H);
            float dcf = has - o9;
            float confsq = dcf * dcf;

            float accA = 5.0f * (dx * dx + dy * dy + swd * swd + shd * shd)
                       + 0.5f * confsq;
            accC += 0.5f * confsq + cls;

            atomicAdd(&sA_blk[rc], accA);
        }
        __syncthreads();                  /* stage readers done -> refillable */

        if (tid == 0) {
            int t = atomicAdd(&g_tile, 1);
            sTile[stg] = t;
            if (t < NT_) ISSUE_TILE(t, stg);
        }
        __syncthreads();                  /* sTile visible for iter k+2 */
    }

    /* block reduction of C (4 warps) */
#pragma unroll
    for (int off = 16; off > 0; off >>= 1)
        accC += __shfl_down_sync(0xFFFFFFFFu, accC, off);
    if ((tid & 31) == 0) atomicAdd(&sC_blk, accC);
    __syncthreads();

    if (tid < SS_) atomicAdd(&g_A[tid], sA_blk[tid]);
    if (tid == 64) atomicAdd(&g_C, sC_blk);

    /* ---------------- grid-wide barrier ---------------- */
    __threadfence();                      /* every thread: g_has visible */
    __syncthreads();
    if (tid == 0) {
        atomicAdd(&g_barrier, 1);
        while (*(volatile int*)&g_barrier < NBLK_) { __nanosleep(32); }
    }
    __syncthreads();

    /* ---------------- phase 2: 256 blocks x 64 batches ---------------- */
    int arrive_old = 0;
    if (bid < OUT_BLKS_) {
        if (tid < SS_) sAfin[tid] = g_A[tid];
        if (tid == 64) sAfin[SS_] = g_C;

        const float4* gh4 = (const float4*)(g_has + (size_t)bid * BPO_ * SS_);
        float4* sh4 = (float4*)dynsmem;
#pragma unroll
        for (int j = 0; j < 7; j++) {
            int idx = j * BLK_ + tid;
            if (idx < OUT_V) sh4[idx] = gh4[idx];
        }
        __syncthreads();

        if (tid == 0) arrive_old = atomicAdd(&g_done, 1);

        if (tid < BPO_) {
            const float* hb = dynsmem + tid * SS_;   /* stride 49: conflict-free */
            float s = 0.0f;
#pragma unroll
            for (int r = 0; r < SS_; r++)
                s += hb[r] * sAfin[r];
            lossOut[bid * BPO_ + tid] = s + sAfin[SS_];
        }
    } else {
        if (tid == 0) arrive_old = atomicAdd(&g_done, 1);
    }

    /* last arriving block resets everything for the next replay */
    if (tid == 0 && arrive_old == NBLK_ - 1) {
#pragma unroll
        for (int i = 0; i < SS_; i++) g_A[i] = 0.0f;
        g_C = 0.0f;
        g_tile = 0;
        g_barrier = 0;
        g_done = 0;
    }
}

extern "C" void kernel_launch(void* const* d_in, const int* in_sizes, int n_in,
                              void* d_out, int out_size)
{
    const float* o  = (const float*)d_in[0];
    const float* t  = (const float*)d_in[1];
    const void*  iw = d_in[2];
    const void*  ih = d_in[3];

    cudaFuncSetAttribute(yolo_kernel,
                         cudaFuncAttributeMaxDynamicSharedMemorySize, SMEM_BYTES);
    yolo_kernel<<<NBLK_, BLK_, SMEM_BYTES>>>(o, t, iw, ih, (float*)d_out);
}